// round 15
// baseline (speedup 1.0000x reference)
#include <cuda_runtime.h>
#include <cuda_fp16.h>
#include <cstdint>

#define B_    4
#define CIN   128
#define COUT  128
#define H_    64
#define W_    64
#define T_    16
#define SS    512
#define NPOS  (H_ * W_ * T_)

#define NTILES 2048
#define GRID   304          // 2 CTAs per SM x 152 SMs (GB300)

// ---- static device scratch (no cudaMalloc allowed) ----
__device__ float    g_s[B_ * CIN];
__device__ float    g_w2[COUT * CIN];
__device__ float    g_siginv[B_ * COUT];
// A in fragment order: [b][chunk 0..7][tap 0..8][mtile 0..7][lane 0..31] x uint4
__device__ uint4    g_wtf[(size_t)B_ * 8 * 9 * 8 * 32];
// X with k-half pairs adjacent: per (b, chunk, q): NPOS pos x {slot0, slot1}
// = 2*NPOS fp16x2 words = NPOS/2 uint4 units (each unit = 2 pos x 2 slots).
__device__ uint4    g_xq[(size_t)B_ * 8 * 4 * (NPOS / 2)];

__device__ __forceinline__ uint32_t packh2(float lo, float hi) {
    __half2 h = __floats2half2_rn(lo, hi);
    uint32_t u;
    memcpy(&u, &h, 4);
    return u;
}

__device__ __forceinline__ uint32_t smem_u32(const void* p) {
    uint32_t a;
    asm("{ .reg .u64 t; cvta.to.shared.u64 t, %1; cvt.u32.u64 %0, t; }" : "=r"(a) : "l"(p));
    return a;
}

__device__ __forceinline__ void cp16(uint32_t dst, const void* src) {
    asm volatile("cp.async.cg.shared.global [%0], [%1], 16;"
                 :: "r"(dst), "l"(src) : "memory");
}
__device__ __forceinline__ void cp16p(uint32_t dst, const void* src, int ok) {
    asm volatile("cp.async.cg.shared.global [%0], [%1], 16, %2;"
                 :: "r"(dst), "l"(src), "r"(ok ? 16 : 0) : "memory");
}

// ---- mbarrier helpers ----
#define MBAR_INIT(a, n) \
    asm volatile("mbarrier.init.shared.b64 [%0], %1;" :: "r"(a), "r"(n) : "memory")
#define MBAR_ARRIVE(a) \
    asm volatile("mbarrier.arrive.shared.b64 _, [%0];" :: "r"(a) : "memory")
#define CPASYNC_MBAR_ARRIVE(a) \
    asm volatile("cp.async.mbarrier.arrive.noinc.shared.b64 [%0];" :: "r"(a) : "memory")

__device__ __forceinline__ void mbar_wait(uint32_t mbar, uint32_t parity) {
    asm volatile(
        "{\n\t.reg .pred P;\n\t"
        "WL_%=:\n\t"
        "mbarrier.try_wait.parity.acquire.cta.shared::cta.b64 P, [%0], %1, 0x989680;\n\t"
        "@P bra.uni WD_%=;\n\t"
        "bra.uni WL_%=;\n\t"
        "WD_%=:\n\t}"
        :: "r"(mbar), "r"(parity) : "memory");
}

// ---------------------------------------------------------------------------
// Prologue kernels
// ---------------------------------------------------------------------------
__global__ void k_style(const float* __restrict__ style,
                        const float* __restrict__ style_w,
                        const float* __restrict__ style_b) {
    int wg = blockIdx.x * 8 + (threadIdx.x >> 5);
    int lane = threadIdx.x & 31;
    int b = wg >> 7, i = wg & 127;
    const float* st = style + (size_t)b * SS;
    const float* sw = style_w + (size_t)i * SS;
    float acc = 0.f;
#pragma unroll
    for (int r = 0; r < 16; ++r) acc += st[lane + 32 * r] * sw[lane + 32 * r];
#pragma unroll
    for (int o = 16; o; o >>= 1) acc += __shfl_xor_sync(~0u, acc, o);
    if (lane == 0) g_s[b * CIN + i] = acc + style_b[i];
}

__global__ void k_w2(const float* __restrict__ weight) {
    int i = blockIdx.x, o = threadIdx.x;
    const float* wp = weight + ((size_t)o * CIN + i) * 9;
    float wsq = 0.f;
#pragma unroll
    for (int tap = 0; tap < 9; ++tap) { float w = wp[tap]; wsq += w * w; }
    g_w2[o * CIN + i] = wsq;
}

__global__ void k_sig2() {
    int wg = blockIdx.x * 8 + (threadIdx.x >> 5);
    int lane = threadIdx.x & 31;
    int b = wg >> 7, o = wg & 127;
    float acc = 0.f;
#pragma unroll
    for (int r = 0; r < 4; ++r) {
        int i = lane + 32 * r;
        float s = g_s[b * CIN + i];
        acc += g_w2[o * CIN + i] * s * s;
    }
#pragma unroll
    for (int off = 16; off; off >>= 1) acc += __shfl_xor_sync(~0u, acc, off);
    if (lane == 0) g_siginv[b * COUT + o] = rsqrtf(acc + 1e-8f);
}

// Build fragment-ordered modulated weights.
__global__ void k_wfrag(const float* __restrict__ weight) {
    int c   = blockIdx.x / 9;
    int tap = blockIdx.x - c * 9;
    int b   = blockIdx.y;
    int tid = threadIdx.x;
    int lane = tid & 31, mt = tid >> 5;
    int q = lane & 3, g = lane >> 2;

    int cout1 = mt * 16 + g;
    int cout2 = cout1 + 8;
    int ciA = c * 16 + 2 * q;
    int ciB = ciA + 8;

    float sA0 = g_s[b * CIN + ciA],     sA1 = g_s[b * CIN + ciA + 1];
    float sB0 = g_s[b * CIN + ciB],     sB1 = g_s[b * CIN + ciB + 1];

    const float* w = weight;
    uint4 o;
    o.x = packh2(w[((size_t)cout1 * CIN + ciA) * 9 + tap] * sA0,
                 w[((size_t)cout1 * CIN + ciA + 1) * 9 + tap] * sA1);
    o.y = packh2(w[((size_t)cout2 * CIN + ciA) * 9 + tap] * sA0,
                 w[((size_t)cout2 * CIN + ciA + 1) * 9 + tap] * sA1);
    o.z = packh2(w[((size_t)cout1 * CIN + ciB) * 9 + tap] * sB0,
                 w[((size_t)cout1 * CIN + ciB + 1) * 9 + tap] * sB1);
    o.w = packh2(w[((size_t)cout2 * CIN + ciB) * 9 + tap] * sB0,
                 w[((size_t)cout2 * CIN + ciB + 1) * 9 + tap] * sB1);
    g_wtf[(((size_t)(b * 8 + c) * 72) + tap * 8 + mt) * 32 + lane] = o;
}

// Pack x -> g_xq (fragment-pair layout).
__global__ void k_xpack(const float* __restrict__ x) {
    unsigned gt = blockIdx.x * 256 + threadIdx.x;
    unsigned pos4 = gt & (NPOS / 4 - 1);
    unsigned idx  = gt >> 14;
    unsigned q = idx & 3;
    unsigned c = (idx >> 2) & 7;
    unsigned b = idx >> 5;
    unsigned r0 = 16 * c + 2 * q;

    const float4 v00 = *reinterpret_cast<const float4*>(
        x + (size_t)(b * CIN + r0)     * NPOS + pos4 * 4);
    const float4 v01 = *reinterpret_cast<const float4*>(
        x + (size_t)(b * CIN + r0 + 1) * NPOS + pos4 * 4);
    const float4 v10 = *reinterpret_cast<const float4*>(
        x + (size_t)(b * CIN + r0 + 8) * NPOS + pos4 * 4);
    const float4 v11 = *reinterpret_cast<const float4*>(
        x + (size_t)(b * CIN + r0 + 9) * NPOS + pos4 * 4);

    uint4 u0, u1;
    u0.x = packh2(v00.x, v01.x); u0.y = packh2(v10.x, v11.x);
    u0.z = packh2(v00.y, v01.y); u0.w = packh2(v10.y, v11.y);
    u1.x = packh2(v00.z, v01.z); u1.y = packh2(v10.z, v11.z);
    u1.z = packh2(v00.w, v01.w); u1.w = packh2(v10.w, v11.w);

    uint4* dst = g_xq + (size_t)idx * (NPOS / 2) + pos4 * 2;
    dst[0] = u0;
    dst[1] = u1;
}

// ---------------------------------------------------------------------------
// Main conv: PERSISTENT CTAs. Each CTA loops over tiles (stride GRID) with a
// continuous mbarrier double-buffer pipeline across tile boundaries.
// CTA 128 thr = 4 warps (2M x 2N), warp tile 64x64, tile 128x128, 8 chunks.
// ---------------------------------------------------------------------------
#define SA_WORDS 9216
#define SXP      968
#define SX_WORDS (4 * SXP)
#define STAGE_WORDS (SA_WORDS + SX_WORDS)
#define MB_BYTES 64
#define SMEM_BYTES (2 * STAGE_WORDS * 4 + MB_BYTES)   // 104768

__global__ void __launch_bounds__(128)
k_conv(const float* __restrict__ noise,
       const float* __restrict__ noise_param,
       const float* __restrict__ bias_param,
       float* __restrict__ out) {
    extern __shared__ uint32_t smem[];
    const uint32_t sb = smem_u32(smem);
    const uint32_t mb_full0  = sb + 2 * STAGE_WORDS * 4;
    const uint32_t mb_full1  = mb_full0 + 8;
    const uint32_t mb_empty0 = mb_full0 + 16;
    const uint32_t mb_empty1 = mb_full0 + 24;

    const int tid  = threadIdx.x;
    const int lane = tid & 31;
    const int wid  = tid >> 5;
    const int g    = lane >> 2;
    const int q    = lane & 3;
    const int mwarp = (wid >> 1) * 64;
    const int nwarp = (wid & 1) * 64;
    const int mt0   = (wid >> 1) * 4;

    const int bid = blockIdx.x;
    const int ntile = (NTILES - bid + GRID - 1) / GRID;   // tiles for this CTA
    const int total = ntile * 8;                          // global chunk count

    if (tid == 0) {
        MBAR_INIT(mb_full0, 128);
        MBAR_INIT(mb_full1, 128);
        MBAR_INIT(mb_empty0, 128);
        MBAR_INIT(mb_empty1, 128);
    }
    __syncthreads();

    float acc[4][8][4];
#pragma unroll
    for (int mf = 0; mf < 4; ++mf)
#pragma unroll
        for (int nf = 0; nf < 8; ++nf)
#pragma unroll
            for (int r = 0; r < 4; ++r) acc[mf][nf][r] = 0.f;

    // ---- stage global chunk gc into buffer s ----
    auto stage_load = [&](int gc, int s) {
        const int t  = bid + (gc >> 3) * GRID;
        const int c  = gc & 7;
        const int tb = t >> 9;
        const int th = (t >> 3) & 63;
        const int tw = (t & 7) * 8;
        const uint32_t sa = sb + (uint32_t)(s * STAGE_WORDS) * 4;
        const uint32_t sx = sa + SA_WORDS * 4;
        const uint4* asrc = g_wtf + (size_t)(tb * 8 + c) * 2304;
#pragma unroll
        for (int i = 0; i < 18; ++i) {
            int li = tid + i * 128;
            cp16(sa + (uint32_t)li * 16, asrc + li);
        }
        const uint4* xbase = g_xq + (size_t)(tb * 32 + c * 4) * (NPOS / 2);
        for (int li = tid; li < 960; li += 128) {
            int qq = li / 240;
            int r  = li - qq * 240;
            int dh = r / 80;
            int rr = r - dh * 80;
            int wl = rr >> 3;
            int t2 = rr & 7;
            int gh = th + dh - 1;
            int gw = tw + wl - 1;
            int ok = ((unsigned)gh < (unsigned)H_) & ((unsigned)gw < (unsigned)W_);
            int ghc = ok ? gh : 0;
            int gwc = ok ? gw : 0;
            const uint4* src = xbase + (size_t)qq * (NPOS / 2)
                               + (ghc * W_ + gwc) * 8 + t2;
            uint32_t dst = sx + (uint32_t)(qq * SXP + 32 * (dh * 10 + wl) + 4 * t2) * 4;
            cp16p(dst, src, ok);
        }
    };

    auto compute = [&](int s) {
        const uint32_t* sA = smem + s * STAGE_WORDS;
        const uint4* sa4 = reinterpret_cast<const uint4*>(sA);
        const uint2* sx2 = reinterpret_cast<const uint2*>(sA + SA_WORDS);
#pragma unroll
        for (int kh = 0; kh < 3; ++kh) {
            uint32_t b0[12], b1[12];
            const uint2* bp = sx2 + q * (SXP / 2) + kh * 160 + nwarp + g;
#pragma unroll
            for (int f = 0; f < 12; ++f) {
                uint2 bv = bp[f * 8];
                b0[f] = bv.x;
                b1[f] = bv.y;
            }
#pragma unroll
            for (int kw = 0; kw < 3; ++kw) {
                const int tap = kh * 3 + kw;
                uint4 a[4];
#pragma unroll
                for (int mf = 0; mf < 4; ++mf)
                    a[mf] = sa4[(tap * 8 + mt0 + mf) * 32 + lane];
#pragma unroll
                for (int mf = 0; mf < 4; ++mf) {
#pragma unroll
                    for (int nf = 0; nf < 8; ++nf) {
                        const int f = kw * 2 + nf;
                        asm volatile(
                            "mma.sync.aligned.m16n8k16.row.col.f32.f16.f16.f32 "
                            "{%0,%1,%2,%3}, {%4,%5,%6,%7}, {%8,%9}, {%0,%1,%2,%3};"
                            : "+f"(acc[mf][nf][0]), "+f"(acc[mf][nf][1]),
                              "+f"(acc[mf][nf][2]), "+f"(acc[mf][nf][3])
                            : "r"(a[mf].x), "r"(a[mf].y), "r"(a[mf].z), "r"(a[mf].w),
                              "r"(b0[f]), "r"(b1[f]));
                    }
                }
            }
        }
    };

    // per-tile epilogue: demodulate + noise + bias, then reset acc
    auto epilogue = [&](int t) {
        const int tb = t >> 9;
        const int th = (t >> 3) & 63;
        const int tw = (t & 7) * 8;
#pragma unroll
        for (int nf = 0; nf < 8; ++nf) {
            int n  = nwarp + nf * 8 + q * 2;
            int wl = n >> 4;
            int tt = n & 15;
            float2 nz = *reinterpret_cast<const float2*>(
                noise + (((size_t)tb * H_ + th) * W_ + tw + wl) * T_ + tt);
#pragma unroll
            for (int mf = 0; mf < 4; ++mf) {
#pragma unroll
                for (int hf = 0; hf < 2; ++hf) {
                    int m = mwarp + mf * 16 + g + hf * 8;
                    float si = g_siginv[tb * COUT + m];
                    float np = noise_param[m];
                    float bp = bias_param[m];
                    float2 r;
                    r.x = acc[mf][nf][hf * 2 + 0] * si + np * nz.x + bp;
                    r.y = acc[mf][nf][hf * 2 + 1] * si + np * nz.y + bp;
                    *reinterpret_cast<float2*>(
                        out + ((((size_t)tb * COUT + m) * H_ + th) * W_ + tw + wl) * T_ + tt) = r;
                    acc[mf][nf][hf * 2 + 0] = 0.f;
                    acc[mf][nf][hf * 2 + 1] = 0.f;
                }
            }
        }
    };

    // ---- continuous pipeline over all tiles of this CTA ----
    stage_load(0, 0);
    CPASYNC_MBAR_ARRIVE(mb_full0);
    stage_load(1, 1);
    CPASYNC_MBAR_ARRIVE(mb_full1);

#pragma unroll 1
    for (int gc = 0; gc < total; ++gc) {
        const int s = gc & 1;
        const uint32_t fullb  = s ? mb_full1 : mb_full0;
        const uint32_t emptyb = s ? mb_empty1 : mb_empty0;
        const uint32_t par = (gc >> 1) & 1;

        mbar_wait(fullb, par);
        compute(s);
        MBAR_ARRIVE(emptyb);
        if (gc + 2 < total) {
            mbar_wait(emptyb, par);
            stage_load(gc + 2, s);
            CPASYNC_MBAR_ARRIVE(fullb);
        }
        if ((gc & 7) == 7)
            epilogue(bid + (gc >> 3) * GRID);   // overlaps with next-tile loads
    }
}

// ---------------------------------------------------------------------------
// Launch. inputs: x, style, noise, weight, style_w, style_b, noise_param,
//                 bias_param
// ---------------------------------------------------------------------------
extern "C" void kernel_launch(void* const* d_in, const int* in_sizes, int n_in,
                              void* d_out, int out_size) {
    const float* x           = (const float*)d_in[0];
    const float* style       = (const float*)d_in[1];
    const float* noise       = (const float*)d_in[2];
    const float* weight      = (const float*)d_in[3];
    const float* style_w     = (const float*)d_in[4];
    const float* style_b     = (const float*)d_in[5];
    const float* noise_param = (const float*)d_in[6];
    const float* bias_param  = (const float*)d_in[7];
    float* out = (float*)d_out;

    k_style<<<64, 256>>>(style, style_w, style_b);
    k_w2<<<CIN, COUT>>>(weight);
    k_sig2<<<64, 256>>>();
    k_wfrag<<<dim3(72, B_), 256>>>(weight);
    k_xpack<<<8192, 256>>>(x);

    cudaFuncSetAttribute(k_conv, cudaFuncAttributeMaxDynamicSharedMemorySize,
                         SMEM_BYTES);
    k_conv<<<GRID, 128, SMEM_BYTES>>>(noise, noise_param, bias_param, out);
}